// round 4
// baseline (speedup 1.0000x reference)
#include <cuda_runtime.h>
#include <cuda_bf16.h>
#include <cstdint>

// ---------------- problem constants ----------------
#define N_TOT 16384
#define D_DIM 512
#define BMs 128                   // stripe rows per CTA (A resident)
#define BNt 256                   // cols per B tile
#define BK 64                     // K per inner iter (128 bytes of bf16)
#define NTILE (N_TOT / BNt)       // 64 B tiles per sweep
#define KITER (D_DIM / BK)        // 8
#define TOT_ITERS (NTILE * KITER) // 512
#define NCTA (N_TOT / BMs)        // 128 persistent CTAs
#define A_BYTES (BMs * D_DIM * 2)         // 131072
#define A_SEC (BMs * 128)                 // 16384 bytes per k-chunk section
#define B_STAGE (BNt * 128)               // 32768
#define SMEM_BYTES (A_BYTES + 2 * B_STAGE) // 196608

// ---------------- scratch ----------------
__device__ __align__(256) __nv_bfloat16 g_A[N_TOT * D_DIM];
__device__ __align__(256) __nv_bfloat16 g_B[N_TOT * D_DIM];
__device__ float g_part[NCTA];

// ---------------- helpers ----------------
static __device__ __forceinline__ uint32_t smem_u32(const void* p) {
    uint32_t a;
    asm("{ .reg .u64 t; cvta.to.shared.u64 t, %1; cvt.u32.u64 %0, t; }"
        : "=r"(a) : "l"(p));
    return a;
}
static __device__ __forceinline__ uint32_t swz(uint32_t row, uint32_t kb) {
    return row * 128u + (kb ^ ((row & 7u) << 4));
}
static __device__ __forceinline__ void cp_async16(uint32_t dst, const void* src) {
    asm volatile("cp.async.cg.shared.global [%0], [%1], 16;"
                 :: "r"(dst), "l"(src) : "memory");
}
#define CP_COMMIT() asm volatile("cp.async.commit_group;" ::: "memory")
#define CP_WAIT(n)  asm volatile("cp.async.wait_group %0;" :: "n"(n) : "memory")

static __device__ __forceinline__ void ldsm_x4(uint32_t* r, uint32_t addr) {
    asm volatile("ldmatrix.sync.aligned.m8n8.x4.shared.b16 {%0,%1,%2,%3}, [%4];"
                 : "=r"(r[0]), "=r"(r[1]), "=r"(r[2]), "=r"(r[3]) : "r"(addr));
}
static __device__ __forceinline__ void mma16816(
    float* d, const uint32_t* a, uint32_t b0, uint32_t b1) {
    asm volatile(
        "mma.sync.aligned.m16n8k16.row.col.f32.bf16.bf16.f32 "
        "{%0,%1,%2,%3}, {%4,%5,%6,%7}, {%8,%9}, {%0,%1,%2,%3};"
        : "+f"(d[0]), "+f"(d[1]), "+f"(d[2]), "+f"(d[3])
        : "r"(a[0]), "r"(a[1]), "r"(a[2]), "r"(a[3]), "r"(b0), "r"(b1));
}

// softplus(zn) with tiny-u fast path; u>0.02 only at/near the diagonal
static __device__ __forceinline__ float softplus_zn(float zn) {
    float u = __expf(-fabsf(zn));
    float p = fmaf(-0.5f * u, u, u);
    if (u > 0.02f) p = __logf(1.0f + u);
    return fmaxf(zn, 0.0f) + p;
}

// ---------------- kernel 1: fp32 -> bf16 conversion ----------------
__global__ void __launch_bounds__(256) siglip_convert(
    const float4* __restrict__ img, const float4* __restrict__ txt) {
    int i = blockIdx.x * 256 + threadIdx.x;
    float4 a = img[i];
    float4 t = txt[i];
    __nv_bfloat162 a0 = __float22bfloat162_rn(make_float2(a.x, a.y));
    __nv_bfloat162 a1 = __float22bfloat162_rn(make_float2(a.z, a.w));
    __nv_bfloat162 t0 = __float22bfloat162_rn(make_float2(t.x, t.y));
    __nv_bfloat162 t1 = __float22bfloat162_rn(make_float2(t.z, t.w));
    uint2 wa, wt;
    wa.x = *reinterpret_cast<uint32_t*>(&a0);
    wa.y = *reinterpret_cast<uint32_t*>(&a1);
    wt.x = *reinterpret_cast<uint32_t*>(&t0);
    wt.y = *reinterpret_cast<uint32_t*>(&t1);
    reinterpret_cast<uint2*>(g_A)[i] = wa;
    reinterpret_cast<uint2*>(g_B)[i] = wt;
}

// ---------------- kernel 2: persistent stripe GEMM + fused softplus ----------------
// 128 CTAs. Each: A stripe (128 rows x 512 K) resident in smem; sweep 64 B tiles
// (256 cols each) through a double buffer. 8 warps: wm in {0,1} x wn in {0..3},
// warp tile 64x64, acc[4][8][4] = 128 regs.
__global__ void __launch_bounds__(256, 1)
siglip_gemm(const float* __restrict__ sc, const float* __restrict__ bi) {
    extern __shared__ __align__(1024) char smem[];
    const uint32_t sbA = smem_u32(smem);
    const uint32_t sbB = sbA + A_BYTES;
    const int tid = threadIdx.x;
    const int wid = tid >> 5;
    const int lane = tid & 31;
    const int wm = wid >> 2;          // 0..1
    const int wn = wid & 3;           // 0..3
    const int bid = blockIdx.x;
    const int row0 = bid * BMs;

    // ---- prologue: A stripe (32 chunks/thread) + B tile for iter 0 ----
    {
        const __nv_bfloat16* pA = g_A + (size_t)row0 * D_DIM;
        #pragma unroll
        for (int p = 0; p < 32; p++) {
            int i = tid + p * 256;          // 0..8191
            int r = i >> 6, j = i & 63;     // row, 16B-chunk within row
            cp_async16(sbA + (j >> 3) * A_SEC + swz(r, (j & 7) * 16),
                       pA + r * D_DIM + j * 8);
        }
        #pragma unroll
        for (int p = 0; p < 8; p++) {
            int i = tid + p * 256;          // 0..2047
            int r = i >> 3, j = i & 7;      // B row (col of logits), chunk
            cp_async16(sbB + swz(r, j * 16), g_B + (size_t)r * D_DIM + j * 8);
        }
        CP_COMMIT();
    }

    float acc[4][8][4];
    #pragma unroll
    for (int i = 0; i < 4; i++)
        #pragma unroll
        for (int j = 0; j < 8; j++)
            #pragma unroll
            for (int q = 0; q < 4; q++) acc[i][j][q] = 0.0f;

    const uint32_t lrow = lane & 15;
    const uint32_t lkb  = (lane >> 4) * 16;
    const float s = __ldg(sc);
    const float b = __ldg(bi);
    float total = 0.0f;
    const int diag_tile = bid >> 1;   // the one B tile containing diagonal cols

    #pragma unroll 1
    for (int g = 0; g < TOT_ITERS; g++) {
        const int nt = g >> 3;
        const int kiter = g & 7;
        const int buf = g & 1;

        __syncthreads();   // all warps done reading buf^1 from iter g-1

        // prefetch B(g+1) into buf^1
        if (g + 1 < TOT_ITERS) {
            const int g1 = g + 1;
            const int nt1 = g1 >> 3, k1 = g1 & 7;
            const uint32_t dB = sbB + (g1 & 1) * B_STAGE;
            const __nv_bfloat16* pB = g_B + (size_t)(nt1 * BNt) * D_DIM + k1 * BK;
            #pragma unroll
            for (int p = 0; p < 8; p++) {
                int i = tid + p * 256;
                int r = i >> 3, j = i & 7;
                cp_async16(dB + swz(r, j * 16), pB + r * D_DIM + j * 8);
            }
        }
        CP_COMMIT();
        CP_WAIT(1);        // B(g) (and A on g=0) complete
        __syncthreads();

        const uint32_t sA = sbA + kiter * A_SEC;
        const uint32_t sB = sbB + buf * B_STAGE;

        #pragma unroll
        for (int ks = 0; ks < BK / 16; ks++) {
            const uint32_t kb = ks * 32 + lkb;
            uint32_t a[4][4], bb[4][4];
            #pragma unroll
            for (int mi = 0; mi < 4; mi++)
                ldsm_x4(a[mi], sA + swz(wm * 64 + mi * 16 + lrow, kb));
            #pragma unroll
            for (int jj = 0; jj < 4; jj++)
                ldsm_x4(bb[jj], sB + swz(wn * 64 + jj * 16 + lrow, kb));
            #pragma unroll
            for (int mi = 0; mi < 4; mi++) {
                #pragma unroll
                for (int jj = 0; jj < 4; jj++) {
                    mma16816(acc[mi][jj * 2 + 0], a[mi], bb[jj][0], bb[jj][2]);
                    mma16816(acc[mi][jj * 2 + 1], a[mi], bb[jj][1], bb[jj][3]);
                }
            }
        }

        // ---- per-tile fused epilogue after the last k-chunk ----
        if (kiter == 7) {
            if (nt != diag_tile) {
                // fast path: no diagonal in this tile, zn = logit
                #pragma unroll
                for (int mi = 0; mi < 4; mi++)
                    #pragma unroll
                    for (int nj = 0; nj < 8; nj++)
                        #pragma unroll
                        for (int q = 0; q < 4; q++) {
                            float x = fmaf(s, acc[mi][nj][q], b);
                            total += softplus_zn(x);
                            acc[mi][nj][q] = 0.0f;
                        }
            } else {
                const int rbase = row0 + wm * 64 + (lane >> 2);
                const int cbase = nt * BNt + wn * 64 + (lane & 3) * 2;
                #pragma unroll
                for (int mi = 0; mi < 4; mi++)
                    #pragma unroll
                    for (int nj = 0; nj < 8; nj++)
                        #pragma unroll
                        for (int q = 0; q < 4; q++) {
                            const int rg = rbase + mi * 16 + ((q >> 1) << 3);
                            const int cg = cbase + nj * 8 + (q & 1);
                            float x = fmaf(s, acc[mi][nj][q], b);
                            float zn = (rg == cg) ? -x : x;
                            total += softplus_zn(zn);
                            acc[mi][nj][q] = 0.0f;
                        }
            }
        }
    }

    // ---- CTA reduction, one scalar per CTA ----
    #pragma unroll
    for (int o = 16; o; o >>= 1)
        total += __shfl_xor_sync(0xffffffffu, total, o);
    __syncthreads();
    float* red = reinterpret_cast<float*>(smem);
    if (lane == 0) red[wid] = total;
    __syncthreads();
    if (tid == 0) {
        float t8 = 0.0f;
        #pragma unroll
        for (int w = 0; w < 8; w++) t8 += red[w];
        g_part[bid] = t8;
    }
}

// ---------------- kernel 3: deterministic final reduction ----------------
__global__ void __launch_bounds__(128) siglip_reduce(float* __restrict__ out) {
    __shared__ float sd[128];
    sd[threadIdx.x] = g_part[threadIdx.x];
    __syncthreads();
    #pragma unroll
    for (int st = 64; st > 0; st >>= 1) {
        if (threadIdx.x < st) sd[threadIdx.x] += sd[threadIdx.x + st];
        __syncthreads();
    }
    if (threadIdx.x == 0) out[0] = sd[0] * (1.0f / (float)N_TOT);
}

// ---------------- launch ----------------
extern "C" void kernel_launch(void* const* d_in, const int* in_sizes, int n_in,
                              void* d_out, int out_size) {
    const float4* img = (const float4*)d_in[0];
    const float4* txt = (const float4*)d_in[1];
    const float*  sc  = (const float*)d_in[2];
    const float*  bi  = (const float*)d_in[3];
    float* out = (float*)d_out;

    cudaFuncSetAttribute(siglip_gemm, cudaFuncAttributeMaxDynamicSharedMemorySize, SMEM_BYTES);

    siglip_convert<<<(N_TOT * D_DIM / 4) / 256, 256>>>(img, txt);
    siglip_gemm<<<NCTA, 256, SMEM_BYTES>>>(sc, bi);
    siglip_reduce<<<1, 128>>>(out);
}

// round 5
// speedup vs baseline: 1.2793x; 1.2793x over previous
#include <cuda_runtime.h>
#include <cuda_bf16.h>
#include <cstdint>

// ---------------- problem constants ----------------
#define N_TOT 16384
#define D_DIM 512
#define BM 128
#define BN 128
#define BK 64                     // 64 bf16 = 128 bytes per row-chunk
#define NSTAGE 3
#define NITER (D_DIM / BK)        // 8
#define GXN (N_TOT / BN)          // 128
#define GYN (N_TOT / BM)          // 128
#define A_STAGE_BYTES (BM * 128)  // 16 KB
#define B_STAGE_BYTES (BN * 128)  // 16 KB
#define STAGE_BYTES (A_STAGE_BYTES + B_STAGE_BYTES)   // 32 KB
#define SMEM_BYTES (NSTAGE * STAGE_BYTES)             // 96 KB

// ---------------- scratch (device globals; no allocation allowed) ----------------
__device__ __align__(256) __nv_bfloat16 g_A[N_TOT * D_DIM];
__device__ __align__(256) __nv_bfloat16 g_B[N_TOT * D_DIM];
__device__ float g_part[GXN * GYN];

// ---------------- helpers ----------------
static __device__ __forceinline__ uint32_t smem_u32(const void* p) {
    uint32_t a;
    asm("{ .reg .u64 t; cvta.to.shared.u64 t, %1; cvt.u32.u64 %0, t; }"
        : "=r"(a) : "l"(p));
    return a;
}
static __device__ __forceinline__ uint32_t swz(uint32_t row, uint32_t kb) {
    return row * 128u + (kb ^ ((row & 7u) << 4));
}
static __device__ __forceinline__ void cp_async16(uint32_t dst, const void* src) {
    asm volatile("cp.async.cg.shared.global [%0], [%1], 16;"
                 :: "r"(dst), "l"(src) : "memory");
}
#define CP_COMMIT() asm volatile("cp.async.commit_group;" ::: "memory")
#define CP_WAIT(n)  asm volatile("cp.async.wait_group %0;" :: "n"(n) : "memory")

static __device__ __forceinline__ void ldsm_x4(uint32_t* r, uint32_t addr) {
    asm volatile("ldmatrix.sync.aligned.m8n8.x4.shared.b16 {%0,%1,%2,%3}, [%4];"
                 : "=r"(r[0]), "=r"(r[1]), "=r"(r[2]), "=r"(r[3]) : "r"(addr));
}
static __device__ __forceinline__ void mma16816(
    float* d, const uint32_t* a, uint32_t b0, uint32_t b1) {
    asm volatile(
        "mma.sync.aligned.m16n8k16.row.col.f32.bf16.bf16.f32 "
        "{%0,%1,%2,%3}, {%4,%5,%6,%7}, {%8,%9}, {%0,%1,%2,%3};"
        : "+f"(d[0]), "+f"(d[1]), "+f"(d[2]), "+f"(d[3])
        : "r"(a[0]), "r"(a[1]), "r"(a[2]), "r"(a[3]), "r"(b0), "r"(b1));
}

// softplus(zn) with tiny-u fast path; u > 0.02 only at/near the diagonal
static __device__ __forceinline__ float softplus_zn(float zn) {
    float u = __expf(-fabsf(zn));
    float p = fmaf(-0.5f * u, u, u);
    if (u > 0.02f) p = __logf(1.0f + u);
    return fmaxf(zn, 0.0f) + p;
}

// ---------------- kernel 1: fp32 -> bf16 conversion ----------------
__global__ void __launch_bounds__(256) siglip_convert(
    const float4* __restrict__ img, const float4* __restrict__ txt) {
    int i = blockIdx.x * 256 + threadIdx.x;
    float4 a = img[i];
    float4 t = txt[i];
    __nv_bfloat162 a0 = __float22bfloat162_rn(make_float2(a.x, a.y));
    __nv_bfloat162 a1 = __float22bfloat162_rn(make_float2(a.z, a.w));
    __nv_bfloat162 t0 = __float22bfloat162_rn(make_float2(t.x, t.y));
    __nv_bfloat162 t1 = __float22bfloat162_rn(make_float2(t.z, t.w));
    uint2 wa, wt;
    wa.x = *reinterpret_cast<uint32_t*>(&a0);
    wa.y = *reinterpret_cast<uint32_t*>(&a1);
    wt.x = *reinterpret_cast<uint32_t*>(&t0);
    wt.y = *reinterpret_cast<uint32_t*>(&t1);
    reinterpret_cast<uint2*>(g_A)[i] = wa;
    reinterpret_cast<uint2*>(g_B)[i] = wt;
}

// ---------------- kernel 2: pipelined bf16 HMMA GEMM + fused softplus ----------------
// 4 warps (128 threads): wm = wid>>1 (0..1), wn = wid&1 (0..1); warp tile 64x64.
// acc[4][8][4] = 128 regs. 2 CTAs/SM.
__global__ void __launch_bounds__(128, 2)
siglip_gemm(const float* __restrict__ sc, const float* __restrict__ bi) {
    extern __shared__ __align__(1024) char smem[];
    const uint32_t sb = smem_u32(smem);
    const int tid = threadIdx.x;
    const int wid = tid >> 5;
    const int lane = tid & 31;
    const int wm = wid >> 1;         // 0..1
    const int wn = wid & 1;          // 0..1

    const int row0 = blockIdx.y * BM;
    const int col0 = blockIdx.x * BN;
    const __nv_bfloat16* __restrict__ pA = g_A + (size_t)row0 * D_DIM;
    const __nv_bfloat16* __restrict__ pB = g_B + (size_t)col0 * D_DIM;

    // cp.async coords: 1024 chunks each for A and B => 8 chunks/thread each
    const int crow = tid >> 3;           // 0..15 base row
    const int cj = (tid & 7) * 16;       // byte col within 128B row

    // ---- issue first NSTAGE-1 stages ----
    #pragma unroll
    for (int s = 0; s < NSTAGE - 1; s++) {
        const int kof = s * BK;
        const uint32_t sA = sb + s * STAGE_BYTES;
        const uint32_t sB = sA + A_STAGE_BYTES;
        #pragma unroll
        for (int p = 0; p < 8; p++) {
            int r = crow + p * 16;
            cp_async16(sA + swz(r, cj), pA + r * D_DIM + kof + (cj >> 1));
        }
        #pragma unroll
        for (int p = 0; p < 8; p++) {
            int r = crow + p * 16;
            cp_async16(sB + swz(r, cj), pB + r * D_DIM + kof + (cj >> 1));
        }
        CP_COMMIT();
    }

    float acc[4][8][4];
    #pragma unroll
    for (int i = 0; i < 4; i++)
        #pragma unroll
        for (int j = 0; j < 8; j++)
            #pragma unroll
            for (int q = 0; q < 4; q++) acc[i][j][q] = 0.0f;

    const uint32_t lrow = lane & 15;
    const uint32_t lkb  = (lane >> 4) * 16;

    #pragma unroll 1
    for (int c = 0; c < NITER; c++) {
        CP_WAIT(NSTAGE - 2);
        __syncthreads();

        // prefetch stage c + NSTAGE - 1
        if (c + NSTAGE - 1 < NITER) {
            const int s = (c + NSTAGE - 1) % NSTAGE;
            const int kof = (c + NSTAGE - 1) * BK;
            const uint32_t sA = sb + s * STAGE_BYTES;
            const uint32_t sB = sA + A_STAGE_BYTES;
            #pragma unroll
            for (int p = 0; p < 8; p++) {
                int r = crow + p * 16;
                cp_async16(sA + swz(r, cj), pA + r * D_DIM + kof + (cj >> 1));
            }
            #pragma unroll
            for (int p = 0; p < 8; p++) {
                int r = crow + p * 16;
                cp_async16(sB + swz(r, cj), pB + r * D_DIM + kof + (cj >> 1));
            }
        }
        CP_COMMIT();

        const uint32_t sA = sb + (c % NSTAGE) * STAGE_BYTES;
        const uint32_t sB = sA + A_STAGE_BYTES;

        #pragma unroll
        for (int ks = 0; ks < BK / 16; ks++) {
            const uint32_t kb = ks * 32 + lkb;     // byte col of this k-step
            uint32_t a[4][4], b[4][4];
            #pragma unroll
            for (int mi = 0; mi < 4; mi++)
                ldsm_x4(a[mi], sA + swz(wm * 64 + mi * 16 + lrow, kb));
            #pragma unroll
            for (int jj = 0; jj < 4; jj++)
                ldsm_x4(b[jj], sB + swz(wn * 64 + jj * 16 + lrow, kb));
            #pragma unroll
            for (int mi = 0; mi < 4; mi++) {
                #pragma unroll
                for (int jj = 0; jj < 4; jj++) {
                    mma16816(acc[mi][jj * 2 + 0], a[mi], b[jj][0], b[jj][2]);
                    mma16816(acc[mi][jj * 2 + 1], a[mi], b[jj][1], b[jj][3]);
                }
            }
        }
    }

    // ---- fused epilogue: loss += softplus(-label * (scale*d + bias)) ----
    const float s = __ldg(sc);
    const float b = __ldg(bi);
    float total = 0.0f;

    const int rbase = row0 + wm * 64 + (lane >> 2);
    const int cbase = col0 + wn * 64 + (lane & 3) * 2;
    const bool has_diag = (blockIdx.x == blockIdx.y);   // BM == BN

    if (!has_diag) {
        #pragma unroll
        for (int mi = 0; mi < 4; mi++)
            #pragma unroll
            for (int nj = 0; nj < 8; nj++)
                #pragma unroll
                for (int q = 0; q < 4; q++)
                    total += softplus_zn(fmaf(s, acc[mi][nj][q], b));
    } else {
        #pragma unroll
        for (int mi = 0; mi < 4; mi++)
            #pragma unroll
            for (int nj = 0; nj < 8; nj++)
                #pragma unroll
                for (int q = 0; q < 4; q++) {
                    const int rg = rbase + mi * 16 + ((q >> 1) << 3);
                    const int cg = cbase + nj * 8 + (q & 1);
                    float x = fmaf(s, acc[mi][nj][q], b);
                    float zn = (rg == cg) ? -x : x;
                    total += softplus_zn(zn);
                }
    }

    #pragma unroll
    for (int o = 16; o; o >>= 1)
        total += __shfl_xor_sync(0xffffffffu, total, o);

    __syncthreads();
    float* red = reinterpret_cast<float*>(smem);
    if (lane == 0) red[wid] = total;
    __syncthreads();
    if (tid == 0) {
        g_part[blockIdx.y * GXN + blockIdx.x] = red[0] + red[1] + red[2] + red[3];
    }
}

// ---------------- kernel 3: deterministic final reduction ----------------
__global__ void __launch_bounds__(256) siglip_reduce(float* __restrict__ out) {
    __shared__ float sd[256];
    float v = 0.0f;
    #pragma unroll
    for (int k = 0; k < (GXN * GYN) / 256; k++)
        v += g_part[threadIdx.x + k * 256];
    sd[threadIdx.x] = v;
    __syncthreads();
    #pragma unroll
    for (int st = 128; st > 0; st >>= 1) {
        if (threadIdx.x < st) sd[threadIdx.x] += sd[threadIdx.x + st];
        __syncthreads();
    }
    if (threadIdx.x == 0) out[0] = sd[0] * (1.0f / (float)N_TOT);
}

// ---------------- launch ----------------
extern "C" void kernel_launch(void* const* d_in, const int* in_sizes, int n_in,
                              void* d_out, int out_size) {
    const float4* img = (const float4*)d_in[0];
    const float4* txt = (const float4*)d_in[1];
    const float*  sc  = (const float*)d_in[2];
    const float*  bi  = (const float*)d_in[3];
    float* out = (float*)d_out;

    cudaFuncSetAttribute(siglip_gemm, cudaFuncAttributeMaxDynamicSharedMemorySize, SMEM_BYTES);

    siglip_convert<<<(N_TOT * D_DIM / 4) / 256, 256>>>(img, txt);
    siglip_gemm<<<dim3(GXN, GYN), 128, SMEM_BYTES>>>(sc, bi);
    siglip_reduce<<<1, 256>>>(out);
}